// round 2
// baseline (speedup 1.0000x reference)
#include <cuda_runtime.h>
#include <cuda_bf16.h>
#include <math.h>

// Problem shapes (fixed by the dataset)
#define BQ   2
#define NN   50000
#define DD   128
#define ROWS (BQ * NN)          // 100000 rows of [D]

// Scratch: m = H@W, agg = scatter-add accumulator. 51.2 MB each.
__device__ float g_m[(size_t)ROWS * DD];
__device__ float g_agg[(size_t)ROWS * DD];
__device__ int   g_idx_is64;    // 1 if src/dst are int64, 0 if int32

// ---------------------------------------------------------------------------
// Kernel 0: detect index dtype. If the buffer holds int64 values < 2^31, every
// odd 32-bit word (high half) is 0. If it holds int32 values in [0, 50000),
// the odd words are random nonzero with overwhelming probability.
// ---------------------------------------------------------------------------
__global__ void detect_idx_kernel(const unsigned int* __restrict__ src_raw)
{
    unsigned int acc = 0;
#pragma unroll
    for (int i = 0; i < 16; i++) acc |= src_raw[2 * i + 1];
    g_idx_is64 = (acc == 0u) ? 1 : 0;
}

// ---------------------------------------------------------------------------
// Kernel 1: m = H @ W  (fp32, 128x128 block tile, K-tiled by 32, 8x8/thread)
// Also zeroes g_agg (grid-stride) so the scatter kernel can atomically add.
// ---------------------------------------------------------------------------
__global__ __launch_bounds__(256) void gemm_zero_kernel(
    const float* __restrict__ Hm, const float* __restrict__ W)
{
    // Zero a slice of g_agg (completes before scatter via kernel boundary)
    {
        float4* aggv = (float4*)g_agg;
        const int total4 = ROWS * DD / 4;
        for (int i = blockIdx.x * 256 + threadIdx.x; i < total4; i += gridDim.x * 256)
            aggv[i] = make_float4(0.f, 0.f, 0.f, 0.f);
    }

    __shared__ float Hs[128][32];   // H tile  [rows][k]
    __shared__ float Ws[32][128];   // W tile  [k][cols]

    const int tid = threadIdx.x;
    const int tx = tid & 15;        // 16 col-groups of 8
    const int ty = tid >> 4;        // 16 row-groups of 8
    const int rowBase = blockIdx.x * 128;

    float acc[8][8];
#pragma unroll
    for (int i = 0; i < 8; i++)
#pragma unroll
        for (int j = 0; j < 8; j++) acc[i][j] = 0.f;

    for (int kt = 0; kt < 4; kt++) {
        // Load H tile: 128 rows x 32 k  (1024 float4, 4 per thread)
        {
            const int r0 = tid >> 3;       // 0..31
            const int qc = tid & 7;        // 0..7  (float4 col)
#pragma unroll
            for (int jj = 0; jj < 4; jj++) {
                const int r = r0 + jj * 32;
                const int grow = rowBase + r;
                float4 hv = make_float4(0.f, 0.f, 0.f, 0.f);
                if (grow < ROWS)
                    hv = *(const float4*)(Hm + (size_t)grow * DD + kt * 32 + qc * 4);
                *(float4*)&Hs[r][qc * 4] = hv;
            }
        }
        // Load W tile: 32 k x 128 cols (1024 float4, 4 per thread)
        {
            const int kr0 = tid >> 5;      // 0..7
            const int wc = tid & 31;       // 0..31 (float4 col)
#pragma unroll
            for (int jj = 0; jj < 4; jj++) {
                const int kr = kr0 + jj * 8;
                *(float4*)&Ws[kr][wc * 4] =
                    *(const float4*)(W + (size_t)(kt * 32 + kr) * DD + wc * 4);
            }
        }
        __syncthreads();

#pragma unroll
        for (int k = 0; k < 32; k++) {
            const float4 b0 = *(const float4*)&Ws[k][tx * 8];
            const float4 b1 = *(const float4*)&Ws[k][tx * 8 + 4];
#pragma unroll
            for (int i = 0; i < 8; i++) {
                const float a = Hs[ty * 8 + i][k];
                acc[i][0] = fmaf(a, b0.x, acc[i][0]);
                acc[i][1] = fmaf(a, b0.y, acc[i][1]);
                acc[i][2] = fmaf(a, b0.z, acc[i][2]);
                acc[i][3] = fmaf(a, b0.w, acc[i][3]);
                acc[i][4] = fmaf(a, b1.x, acc[i][4]);
                acc[i][5] = fmaf(a, b1.y, acc[i][5]);
                acc[i][6] = fmaf(a, b1.z, acc[i][6]);
                acc[i][7] = fmaf(a, b1.w, acc[i][7]);
            }
        }
        __syncthreads();
    }

    // Store m
#pragma unroll
    for (int i = 0; i < 8; i++) {
        const int grow = rowBase + ty * 8 + i;
        if (grow < ROWS) {
            float* mp = g_m + (size_t)grow * DD + tx * 8;
            *(float4*)(mp)     = make_float4(acc[i][0], acc[i][1], acc[i][2], acc[i][3]);
            *(float4*)(mp + 4) = make_float4(acc[i][4], acc[i][5], acc[i][6], acc[i][7]);
        }
    }
}

// ---------------------------------------------------------------------------
// Kernel 2: edge scatter-add. One warp per (batch, edge): 32 lanes x float4
// = 128 floats. atomicAdd with unused return compiles to REDG (no-return).
// Index dtype (int32 vs int64) selected at runtime via g_idx_is64.
// ---------------------------------------------------------------------------
__global__ __launch_bounds__(256) void scatter_kernel(
    const void* __restrict__ src, const void* __restrict__ dst, int E)
{
    const int gw = (blockIdx.x * 256 + threadIdx.x) >> 5;
    const int lane = threadIdx.x & 31;
    if (gw >= 2 * E) return;
    const int b = (gw >= E) ? 1 : 0;
    const int e = gw - b * E;

    const int is64 = g_idx_is64;   // uniform branch
    int s, d;
    if (is64) {
        s = (int)((const long long*)src)[e];
        d = (int)((const long long*)dst)[e];
    } else {
        s = ((const int*)src)[e];
        d = ((const int*)dst)[e];
    }
    if ((unsigned)s >= (unsigned)NN || (unsigned)d >= (unsigned)NN) return;

    const float4 v = ((const float4*)(g_m + ((size_t)(b * NN + s)) * DD))[lane];
    float* dp = g_agg + ((size_t)(b * NN + d)) * DD + (lane << 2);
    atomicAdd(dp + 0, v.x);
    atomicAdd(dp + 1, v.y);
    atomicAdd(dp + 2, v.z);
    atomicAdd(dp + 3, v.w);
}

// ---------------------------------------------------------------------------
// Kernel 3: out = LayerNorm(H + gelu(agg)) ; one warp per row.
// ---------------------------------------------------------------------------
__device__ __forceinline__ float gelu_exact(float x) {
    return 0.5f * x * (1.0f + erff(x * 0.70710678118654752f));
}

__global__ __launch_bounds__(256) void ln_kernel(
    const float* __restrict__ Hm, const float* __restrict__ gamma,
    const float* __restrict__ beta, float* __restrict__ out)
{
    const int row = blockIdx.x * 8 + (threadIdx.x >> 5);
    if (row >= ROWS) return;
    const int lane = threadIdx.x & 31;

    const float4 a = ((const float4*)g_agg)[(size_t)row * 32 + lane];
    const float4 h = ((const float4*)Hm)[(size_t)row * 32 + lane];

    float4 x;
    x.x = h.x + gelu_exact(a.x);
    x.y = h.y + gelu_exact(a.y);
    x.z = h.z + gelu_exact(a.z);
    x.w = h.w + gelu_exact(a.w);

    float s  = x.x + x.y + x.z + x.w;
    float ss = fmaf(x.x, x.x, fmaf(x.y, x.y, fmaf(x.z, x.z, x.w * x.w)));
#pragma unroll
    for (int o = 16; o > 0; o >>= 1) {
        s  += __shfl_xor_sync(0xFFFFFFFFu, s,  o);
        ss += __shfl_xor_sync(0xFFFFFFFFu, ss, o);
    }
    const float mean = s * (1.0f / 128.0f);
    const float var  = ss * (1.0f / 128.0f) - mean * mean;
    const float rstd = rsqrtf(var + 1e-5f);

    const float4 g  = ((const float4*)gamma)[lane];
    const float4 bt = ((const float4*)beta)[lane];

    float4 o4;
    o4.x = (x.x - mean) * rstd * g.x + bt.x;
    o4.y = (x.y - mean) * rstd * g.y + bt.y;
    o4.z = (x.z - mean) * rstd * g.z + bt.z;
    o4.w = (x.w - mean) * rstd * g.w + bt.w;

    ((float4*)out)[(size_t)row * 32 + lane] = o4;
}

// ---------------------------------------------------------------------------
extern "C" void kernel_launch(void* const* d_in, const int* in_sizes, int n_in,
                              void* d_out, int out_size)
{
    const float* H     = (const float*)d_in[0];
    const void*  src   = d_in[1];
    const void*  dst   = d_in[2];
    const float* W     = (const float*)d_in[3];
    const float* gamma = (const float*)d_in[4];
    const float* beta  = (const float*)d_in[5];
    const int E = in_sizes[1];

    // 0) detect whether src/dst are int32 or int64
    detect_idx_kernel<<<1, 1>>>((const unsigned int*)src);

    // 1) m = H@W  + zero agg
    gemm_zero_kernel<<<(ROWS + 127) / 128, 256>>>(H, W);

    // 2) scatter-add: one warp per (batch, edge)
    const int warps = 2 * E;
    scatter_kernel<<<(warps + 7) / 8, 256>>>(src, dst, E);

    // 3) gelu + residual + LayerNorm
    ln_kernel<<<(ROWS + 7) / 8, 256>>>(H, gamma, beta, (float*)d_out);
}

// round 3
// speedup vs baseline: 2.7333x; 2.7333x over previous
#include <cuda_runtime.h>
#include <cuda_bf16.h>
#include <math.h>

// Problem shapes (fixed by the dataset)
#define BQ   2
#define NN   50000
#define DD   128
#define ROWS (BQ * NN)          // 100000 rows of [D]
#define EMAX 2000000
#define NCHUNK ((NN + 255) / 256)   // 196

// Scratch
__device__ float g_m[(size_t)ROWS * DD];   // m = H@W  (51.2 MB)
__device__ int   g_cnt[NN];                // per-dst edge counts
__device__ int   g_off[NN + 1];            // CSR row offsets
__device__ int   g_cur[NN];                // fill cursors
__device__ int   g_esrc[EMAX];             // src ids grouped by dst
__device__ int   g_chunksum[256];          // scan partials
__device__ int   g_idx_is64;               // 1 if src/dst are int64

// ---------------------------------------------------------------------------
__device__ __forceinline__ int load_idx(const void* p, int e, int is64) {
    return is64 ? (int)((const long long*)p)[e] : ((const int*)p)[e];
}

// Kernel 0: detect index dtype (int64 -> odd 32-bit words all zero) + zero cnt
__global__ void detect_zero_kernel(const unsigned int* __restrict__ src_raw)
{
    const int i = blockIdx.x * 256 + threadIdx.x;
    if (i < NN) g_cnt[i] = 0;
    if (i == 0) {
        unsigned int acc = 0;
#pragma unroll
        for (int k = 0; k < 16; k++) acc |= src_raw[2 * k + 1];
        g_idx_is64 = (acc == 0u) ? 1 : 0;
    }
}

// ---------------------------------------------------------------------------
// Kernel 1: m = H @ W  (fp32, 128x128 block tile, K-tiled by 32, 8x8/thread)
// ---------------------------------------------------------------------------
__global__ __launch_bounds__(256) void gemm_kernel(
    const float* __restrict__ Hm, const float* __restrict__ W)
{
    __shared__ float Hs[128][32];
    __shared__ float Ws[32][128];

    const int tid = threadIdx.x;
    const int tx = tid & 15;
    const int ty = tid >> 4;
    const int rowBase = blockIdx.x * 128;

    float acc[8][8];
#pragma unroll
    for (int i = 0; i < 8; i++)
#pragma unroll
        for (int j = 0; j < 8; j++) acc[i][j] = 0.f;

    for (int kt = 0; kt < 4; kt++) {
        {
            const int r0 = tid >> 3;
            const int qc = tid & 7;
#pragma unroll
            for (int jj = 0; jj < 4; jj++) {
                const int r = r0 + jj * 32;
                const int grow = rowBase + r;
                float4 hv = make_float4(0.f, 0.f, 0.f, 0.f);
                if (grow < ROWS)
                    hv = *(const float4*)(Hm + (size_t)grow * DD + kt * 32 + qc * 4);
                *(float4*)&Hs[r][qc * 4] = hv;
            }
        }
        {
            const int kr0 = tid >> 5;
            const int wc = tid & 31;
#pragma unroll
            for (int jj = 0; jj < 4; jj++) {
                const int kr = kr0 + jj * 8;
                *(float4*)&Ws[kr][wc * 4] =
                    *(const float4*)(W + (size_t)(kt * 32 + kr) * DD + wc * 4);
            }
        }
        __syncthreads();

#pragma unroll
        for (int k = 0; k < 32; k++) {
            const float4 b0 = *(const float4*)&Ws[k][tx * 8];
            const float4 b1 = *(const float4*)&Ws[k][tx * 8 + 4];
#pragma unroll
            for (int i = 0; i < 8; i++) {
                const float a = Hs[ty * 8 + i][k];
                acc[i][0] = fmaf(a, b0.x, acc[i][0]);
                acc[i][1] = fmaf(a, b0.y, acc[i][1]);
                acc[i][2] = fmaf(a, b0.z, acc[i][2]);
                acc[i][3] = fmaf(a, b0.w, acc[i][3]);
                acc[i][4] = fmaf(a, b1.x, acc[i][4]);
                acc[i][5] = fmaf(a, b1.y, acc[i][5]);
                acc[i][6] = fmaf(a, b1.z, acc[i][6]);
                acc[i][7] = fmaf(a, b1.w, acc[i][7]);
            }
        }
        __syncthreads();
    }

#pragma unroll
    for (int i = 0; i < 8; i++) {
        const int grow = rowBase + ty * 8 + i;
        if (grow < ROWS) {
            float* mp = g_m + (size_t)grow * DD + tx * 8;
            *(float4*)(mp)     = make_float4(acc[i][0], acc[i][1], acc[i][2], acc[i][3]);
            *(float4*)(mp + 4) = make_float4(acc[i][4], acc[i][5], acc[i][6], acc[i][7]);
        }
    }
}

// ---------------------------------------------------------------------------
// CSR build: histogram -> 3-phase exclusive scan -> fill
// ---------------------------------------------------------------------------
__global__ __launch_bounds__(256) void hist_kernel(const void* __restrict__ dst, int E)
{
    const int e = blockIdx.x * 256 + threadIdx.x;
    if (e >= E) return;
    const int d = load_idx(dst, e, g_idx_is64);
    if ((unsigned)d < (unsigned)NN) atomicAdd(&g_cnt[d], 1);
}

__global__ __launch_bounds__(256) void scan1_kernel()   // per-256-chunk sums
{
    __shared__ int sh[256];
    const int i = blockIdx.x * 256 + threadIdx.x;
    int v = (i < NN) ? g_cnt[i] : 0;
    sh[threadIdx.x] = v;
    __syncthreads();
#pragma unroll
    for (int s = 128; s > 0; s >>= 1) {
        if (threadIdx.x < s) sh[threadIdx.x] += sh[threadIdx.x + s];
        __syncthreads();
    }
    if (threadIdx.x == 0) g_chunksum[blockIdx.x] = sh[0];
}

__global__ __launch_bounds__(256) void scan2_kernel()   // exclusive scan of chunk sums
{
    __shared__ int sh[256];
    const int t = threadIdx.x;
    int v = (t < NCHUNK) ? g_chunksum[t] : 0;
    sh[t] = v;
    __syncthreads();
#pragma unroll
    for (int o = 1; o < 256; o <<= 1) {
        int add = (t >= o) ? sh[t - o] : 0;
        __syncthreads();
        sh[t] += add;
        __syncthreads();
    }
    if (t < NCHUNK) g_chunksum[t] = sh[t] - v;   // exclusive
}

__global__ __launch_bounds__(256) void scan3_kernel(int E)  // per-element offsets
{
    __shared__ int sh[256];
    const int t = threadIdx.x;
    const int i = blockIdx.x * 256 + t;
    int v = (i < NN) ? g_cnt[i] : 0;
    sh[t] = v;
    __syncthreads();
#pragma unroll
    for (int o = 1; o < 256; o <<= 1) {
        int add = (t >= o) ? sh[t - o] : 0;
        __syncthreads();
        sh[t] += add;
        __syncthreads();
    }
    if (i < NN) {
        const int off = g_chunksum[blockIdx.x] + sh[t] - v;   // exclusive
        g_off[i] = off;
        g_cur[i] = off;
        if (i == NN - 1) g_off[NN] = off + v;
    }
}

__global__ __launch_bounds__(256) void fill_kernel(
    const void* __restrict__ src, const void* __restrict__ dst, int E)
{
    const int e = blockIdx.x * 256 + threadIdx.x;
    if (e >= E) return;
    const int is64 = g_idx_is64;
    const int d = load_idx(dst, e, is64);
    const int s = load_idx(src, e, is64);
    if ((unsigned)d >= (unsigned)NN || (unsigned)s >= (unsigned)NN) return;
    const int pos = atomicAdd(&g_cur[d], 1);
    if (pos < EMAX) g_esrc[pos] = s;
}

// ---------------------------------------------------------------------------
// Fused: per (batch,row) gather-accumulate m[src] rows, then residual+GELU+LN.
// One warp per (b,row); lane covers 4 contiguous floats (float4).
// ---------------------------------------------------------------------------
__device__ __forceinline__ float gelu_exact(float x) {
    return 0.5f * x * (1.0f + erff(x * 0.70710678118654752f));
}

__global__ __launch_bounds__(256) void agg_ln_kernel(
    const float* __restrict__ Hm, const float* __restrict__ gamma,
    const float* __restrict__ beta, float* __restrict__ out)
{
    const int gw = blockIdx.x * 8 + (threadIdx.x >> 5);
    if (gw >= 2 * NN) return;
    const int lane = threadIdx.x & 31;
    const int b   = (gw >= NN) ? 1 : 0;
    const int row = gw - b * NN;

    const int beg = g_off[row];
    const int end = g_off[row + 1];

    float4 a0 = make_float4(0.f, 0.f, 0.f, 0.f);
    float4 a1 = make_float4(0.f, 0.f, 0.f, 0.f);

    const float4* mb = (const float4*)(g_m + (size_t)b * NN * DD);
    int i = beg;
    for (; i + 1 < end; i += 2) {
        const int s0 = g_esrc[i];
        const int s1 = g_esrc[i + 1];
        const float4 v0 = mb[(size_t)s0 * 32 + lane];
        const float4 v1 = mb[(size_t)s1 * 32 + lane];
        a0.x += v0.x; a0.y += v0.y; a0.z += v0.z; a0.w += v0.w;
        a1.x += v1.x; a1.y += v1.y; a1.z += v1.z; a1.w += v1.w;
    }
    if (i < end) {
        const int s0 = g_esrc[i];
        const float4 v0 = mb[(size_t)s0 * 32 + lane];
        a0.x += v0.x; a0.y += v0.y; a0.z += v0.z; a0.w += v0.w;
    }
    a0.x += a1.x; a0.y += a1.y; a0.z += a1.z; a0.w += a1.w;

    const size_t rq = (size_t)(b * NN + row) * 32 + lane;
    const float4 h = ((const float4*)Hm)[rq];

    float4 x;
    x.x = h.x + gelu_exact(a0.x);
    x.y = h.y + gelu_exact(a0.y);
    x.z = h.z + gelu_exact(a0.z);
    x.w = h.w + gelu_exact(a0.w);

    float s  = x.x + x.y + x.z + x.w;
    float ss = fmaf(x.x, x.x, fmaf(x.y, x.y, fmaf(x.z, x.z, x.w * x.w)));
#pragma unroll
    for (int o = 16; o > 0; o >>= 1) {
        s  += __shfl_xor_sync(0xFFFFFFFFu, s,  o);
        ss += __shfl_xor_sync(0xFFFFFFFFu, ss, o);
    }
    const float mean = s * (1.0f / 128.0f);
    const float var  = ss * (1.0f / 128.0f) - mean * mean;
    const float rstd = rsqrtf(var + 1e-5f);

    const float4 g  = ((const float4*)gamma)[lane];
    const float4 bt = ((const float4*)beta)[lane];

    float4 o4;
    o4.x = (x.x - mean) * rstd * g.x + bt.x;
    o4.y = (x.y - mean) * rstd * g.y + bt.y;
    o4.z = (x.z - mean) * rstd * g.z + bt.z;
    o4.w = (x.w - mean) * rstd * g.w + bt.w;

    ((float4*)out)[rq] = o4;
}

// ---------------------------------------------------------------------------
extern "C" void kernel_launch(void* const* d_in, const int* in_sizes, int n_in,
                              void* d_out, int out_size)
{
    const float* H     = (const float*)d_in[0];
    const void*  src   = d_in[1];
    const void*  dst   = d_in[2];
    const float* W     = (const float*)d_in[3];
    const float* gamma = (const float*)d_in[4];
    const float* beta  = (const float*)d_in[5];
    const int E = in_sizes[1];

    const int eb = (E + 255) / 256;

    // 0) detect idx dtype + zero counters
    detect_zero_kernel<<<(NN + 255) / 256, 256>>>((const unsigned int*)src);

    // CSR build (independent of GEMM result; same stream order is fine)
    hist_kernel<<<eb, 256>>>(dst, E);
    scan1_kernel<<<NCHUNK, 256>>>();
    scan2_kernel<<<1, 256>>>();
    scan3_kernel<<<NCHUNK, 256>>>(E);
    fill_kernel<<<eb, 256>>>(src, dst, E);

    // 1) m = H @ W
    gemm_kernel<<<(ROWS + 127) / 128, 256>>>(H, W);

    // 2) fused gather-accumulate + residual + GELU + LayerNorm
    agg_ln_kernel<<<(2 * NN + 7) / 8, 256>>>(H, gamma, beta, (float*)d_out);
}